// round 17
// baseline (speedup 1.0000x reference)
#include <cuda_runtime.h>
#include <math_constants.h>

#define BS   1024
#define DM   512
#define NH   8
#define DK   64
#define HIST 199
#define TT   200
#define TTILE 8
#define NBUF 3
#define NTILES 25
#define PSPLIT 2

// Scratch — referenced ONLY inside device code (host-side use passes the host
// shadow address; ATS makes it silently dereferenceable -> garbage).
__device__ float g_q[BS * DM];                     // 2 MB
__device__ float g_r[BS * NH * DM];                // 16 MB
__device__ float g_pc[BS * PSPLIT * NH * DM];      // 32 MB  unnormalized partial c
__device__ float g_pml[BS * PSPLIT * 16];          // 128 KB m[8], l[8] per (b,s)
__device__ float g_po[2 * BS * DM];                // 4 MB   oproj split-K partials

typedef unsigned long long u64;

// ---- packed f32x2 helpers --------------------------------------------------
__device__ __forceinline__ u64 pack2(float x, float y) {
    u64 r; asm("mov.b64 %0, {%1, %2};" : "=l"(r) : "f"(x), "f"(y)); return r;
}
__device__ __forceinline__ float2 unpack2(u64 v) {
    float2 d; asm("mov.b64 {%0, %1}, %2;" : "=f"(d.x), "=f"(d.y) : "l"(v)); return d;
}
__device__ __forceinline__ void ffma2(u64& acc, u64 a, u64 b) {
    asm("fma.rn.f32x2 %0, %1, %2, %0;" : "+l"(acc) : "l"(a), "l"(b));
}
__device__ __forceinline__ void fmul2(u64& a, u64 b) {
    asm("mul.rn.f32x2 %0, %0, %1;" : "+l"(a) : "l"(b));
}
__device__ __forceinline__ void ldg16(const float* p, u64& a, u64& b) {
    asm volatile("ld.global.nc.v2.b64 {%0, %1}, [%2];" : "=l"(a), "=l"(b) : "l"(p));
}
__device__ __forceinline__ void cp16(void* smem_dst, const void* gsrc) {
    unsigned s = (unsigned)__cvta_generic_to_shared(smem_dst);
    asm volatile("cp.async.cg.shared.global [%0], [%1], 16;" :: "r"(s), "l"(gsrc));
}
__device__ __forceinline__ void cp_commit() { asm volatile("cp.async.commit_group;" ::: "memory"); }
__device__ __forceinline__ void cp_wait1()  { asm volatile("cp.async.wait_group 1;" ::: "memory"); }

__device__ __forceinline__ int swz(int cj, int row) { return 4 * (cj ^ ((row >> 1) & 7)); }

// ============================================================================
// Kernel A: qproj GEMM. 32b x 64d NT, K=512, grid (32,8). 3-buf ring.
// ============================================================================
__global__ void __launch_bounds__(256) k_qproj(
    const float* __restrict__ A, const float* __restrict__ B,
    const float* __restrict__ bias)
{
    __shared__ __align__(16) float Cs[3][32][32];
    __shared__ __align__(16) float Ws[3][64][32];
    const int tid = threadIdx.x;
    const int bB = blockIdx.x * 32;
    const int y  = blockIdx.y;
    const float* Bb = B + (long)y * 64 * 512;
    const int d0 = (tid >> 4) * 4;
    const int b0 = (tid & 15) * 2;

    u64 acc[2][4];
#pragma unroll
    for (int cb = 0; cb < 2; cb++)
#pragma unroll
        for (int dd = 0; dd < 4; dd++) acc[cb][dd] = 0ull;

    const int lrow = tid >> 3, lcj = tid & 7;
    #define QLOAD(buf, kc) do { \
        cp16(&Cs[buf][lrow][swz(lcj, lrow)], \
             A + (long)(bB + lrow) * 512 + (kc) * 32 + lcj * 4); \
        _Pragma("unroll") for (int i = 0; i < 2; i++) { \
            int idx = tid + 256 * i; int d = idx >> 3, cj = idx & 7; \
            cp16(&Ws[buf][d][swz(cj, d)], Bb + (long)d * 512 + (kc) * 32 + cj * 4); \
        } } while (0)

    QLOAD(0, 0); cp_commit();
    QLOAD(1, 1); cp_commit();

    for (int kc = 0; kc < 16; kc++) {
        const int buf = kc % 3;
        cp_wait1();
        __syncthreads();

        if (kc + 2 < 16) QLOAD((kc + 2) % 3, kc + 2);
        cp_commit();

#pragma unroll
        for (int jg = 0; jg < 8; jg++) {
            ulonglong2 wv[4], cv[2];
#pragma unroll
            for (int dd = 0; dd < 4; dd++)
                wv[dd] = *(const ulonglong2*)&Ws[buf][d0 + dd][swz(jg, d0 + dd)];
#pragma unroll
            for (int cb = 0; cb < 2; cb++)
                cv[cb] = *(const ulonglong2*)&Cs[buf][b0 + cb][swz(jg, b0 + cb)];
#pragma unroll
            for (int cb = 0; cb < 2; cb++)
#pragma unroll
                for (int dd = 0; dd < 4; dd++) {
                    ffma2(acc[cb][dd], cv[cb].x, wv[dd].x);
                    ffma2(acc[cb][dd], cv[cb].y, wv[dd].y);
                }
        }
    }

    float4 bb = *(const float4*)&bias[y * 64 + d0];
#pragma unroll
    for (int cb = 0; cb < 2; cb++) {
        float v[4];
#pragma unroll
        for (int dd = 0; dd < 4; dd++) {
            float2 u = unpack2(acc[cb][dd]);
            v[dd] = u.x + u.y;
        }
        float4 o = make_float4(v[0] + bb.x, v[1] + bb.y, v[2] + bb.z, v[3] + bb.w);
        *(float4*)&g_q[(long)(bB + b0 + cb) * 512 + y * 64 + d0] = o;
    }
}

// ============================================================================
// Kernel B: r[b,h,n] = sum_k q[b, h*64+k] * Wk[h*64+k, n]   (NN, K=64)
// ============================================================================
__global__ void __launch_bounds__(256) k_rproj(const float* __restrict__ Wk)
{
    __shared__ __align__(16) float Wks[64][128];
    __shared__ __align__(16) float qs[32][64];
    const int tid = threadIdx.x;
    const int nc = blockIdx.x;
    const int bB = blockIdx.y * 32;
    const int h  = blockIdx.z;

#pragma unroll
    for (int it = 0; it < 8; it++) {
        int idx = tid + 256 * it;
        int k = idx >> 5, n4 = (idx & 31) * 4;
        *(float4*)&Wks[k][n4] = *(const float4*)&Wk[(h * 64 + k) * 512 + nc * 128 + n4];
    }
#pragma unroll
    for (int it = 0; it < 2; it++) {
        int idx = tid + 256 * it;
        int bb = idx >> 4, k4 = (idx & 15) * 4;
        *(float4*)&qs[bb][k4] = *(const float4*)&g_q[(bB + bb) * 512 + h * 64 + k4];
    }
    __syncthreads();

    const int n0 = (tid & 31) * 4;
    const int b0 = (tid >> 5) * 4;
    u64 acc[4][2];
#pragma unroll
    for (int a = 0; a < 4; a++) { acc[a][0] = 0ull; acc[a][1] = 0ull; }

#pragma unroll
    for (int k = 0; k < 64; k++) {
        ulonglong2 w2 = *(const ulonglong2*)&Wks[k][n0];
#pragma unroll
        for (int cb = 0; cb < 4; cb++) {
            float x = qs[b0 + cb][k];
            u64 xx = pack2(x, x);
            ffma2(acc[cb][0], xx, w2.x);
            ffma2(acc[cb][1], xx, w2.y);
        }
    }
#pragma unroll
    for (int cb = 0; cb < 4; cb++) {
        float2 p0 = unpack2(acc[cb][0]), p1 = unpack2(acc[cb][1]);
        float4 o = make_float4(p0.x, p0.y, p1.x, p1.y);
        *(float4*)&g_r[((bB + b0 + cb) * 8 + h) * 512 + nc * 128 + n0] = o;
    }
}

// ============================================================================
// Kernel C: LANE-DISTINCT attention + multi-value butterfly score reduction.
// (identical to R15/R16 except the reduction block: 10 shfl instead of 20)
// ============================================================================
__device__ __forceinline__ void prefetch_tile(
    float* dst, const float* __restrict__ prevb, const float* __restrict__ curb,
    int tile, int tid)
{
#pragma unroll
    for (int i = 0; i < 4; i++) {
        int idx = tid + 256 * i;        // 1024 float4 = 8 rows x 512 floats
        int tr = idx >> 7;
        int c = (idx & 127) * 4;
        int gt = tile * TTILE + tr;     // <= 199 (25*8 = 200 exact)
        const float* src = (gt < HIST) ? (prevb + (long)gt * 512 + c) : (curb + c);
        cp16(dst + tr * 512 + c, src);
    }
}

__device__ __forceinline__ float bfly_sum(float s) {
#pragma unroll
    for (int o = 16; o; o >>= 1) s += __shfl_xor_sync(0xffffffffu, s, o);
    return s;
}

__global__ void __launch_bounds__(256, 2) k_attn(
    const float* __restrict__ cur, const float* __restrict__ prev,
    const float* __restrict__ mask, const float* __restrict__ bk)
{
    __shared__ __align__(16) float xb[NBUF][TTILE][DM];   // 48 KB
    __shared__ float mask_s[TT];
    __shared__ float sb_s[8];

    const int tid = threadIdx.x;
    const int b = blockIdx.x;
    const int w = tid >> 5, lane = tid & 31;
    const int hp = w & 3, par = w >> 2;
    const int h0 = 2 * hp, h1 = 2 * hp + 1;
    const unsigned FULL = 0xffffffffu;

    const float* prevb = prev + (long)b * HIST * 512;
    const float* curb  = cur  + (long)b * 512;

    if (tid < TT) mask_s[tid] = mask[b * TT + tid];
    {   // sb[h] = q[b,h,:]·bk[h,:]; warp w computes head w
        float q1 = g_q[b * 512 + w * 64 + lane];
        float q2 = g_q[b * 512 + w * 64 + 32 + lane];
        float sv = q1 * bk[w * 64 + lane] + q2 * bk[w * 64 + 32 + lane];
        sv = bfly_sum(sv);
        if (lane == 0) sb_s[w] = sv;
    }

    // rf: r[b, h, 4*lane + 128*c] for both heads (16 distinct floats each)
    u64 rf0[8], rf1[8];
    {
        const float* rp0 = &g_r[((long)b * 8 + h0) * 512 + 4 * lane];
        const float* rp1 = &g_r[((long)b * 8 + h1) * 512 + 4 * lane];
#pragma unroll
        for (int c = 0; c < 4; c++) {
            ldg16(rp0 + 128 * c, rf0[2 * c], rf0[2 * c + 1]);
            ldg16(rp1 + 128 * c, rf1[2 * c], rf1[2 * c + 1]);
        }
    }
    u64 acc0[8], acc1[8];
#pragma unroll
    for (int i = 0; i < 8; i++) { acc0[i] = 0ull; acc1[i] = 0ull; }
    float m0 = -CUDART_INF_F, l0 = 0.f;
    float m1 = -CUDART_INF_F, l1 = 0.f;

    // prime 2 tiles
#pragma unroll
    for (int i = 0; i < 2; i++) {
        prefetch_tile(&xb[i][0][0], prevb, curb, i, tid);
        cp_commit();
    }
    __syncthreads();                       // sb_s / mask_s visible
    const float sb0 = sb_s[h0];
    const float sb1 = sb_s[h1];
    const bool hi16 = (lane & 16) != 0;
    const bool hi8  = (lane & 8) != 0;

    for (int tile = 0; tile < NTILES; tile++) {
        const int buf = tile % NBUF;
        cp_wait1();                        // tile's group complete (1 newer pend)
        __syncthreads();                   // the ONLY barrier per tile

        if (tile + 2 < NTILES)
            prefetch_tile(&xb[(tile + 2) % NBUF][0][0], prevb, curb, tile + 2, tid);
        cp_commit();                       // uniform group count

#pragma unroll
        for (int sub = 0; sub < 2; sub++) {
            const int tA = 4 * sub + par;
            const float* rA = &xb[buf][tA][4 * lane];
            const float* rB = &xb[buf][tA + 2][4 * lane];
            u64 xA[8], xB[8];
#pragma unroll
            for (int c = 0; c < 4; c++) {
                ulonglong2 vA = *(const ulonglong2*)(rA + 128 * c);
                ulonglong2 vB = *(const ulonglong2*)(rB + 128 * c);
                xA[2 * c] = vA.x; xA[2 * c + 1] = vA.y;
                xB[2 * c] = vB.x; xB[2 * c + 1] = vB.y;
            }

            u64 a00 = 0ull, a01 = 0ull, a10 = 0ull, a11 = 0ull;
            u64 b00 = 0ull, b01 = 0ull, b10 = 0ull, b11 = 0ull;
#pragma unroll
            for (int i = 0; i < 8; i += 2) {
                ffma2(a00, rf0[i], xA[i]);   ffma2(a01, rf0[i + 1], xA[i + 1]);
                ffma2(a10, rf1[i], xA[i]);   ffma2(a11, rf1[i + 1], xA[i + 1]);
                ffma2(b00, rf0[i], xB[i]);   ffma2(b01, rf0[i + 1], xB[i + 1]);
                ffma2(b10, rf1[i], xB[i]);   ffma2(b11, rf1[i + 1], xB[i + 1]);
            }
            float2 u;
            u = unpack2(a00); float v0 = u.x + u.y; u = unpack2(a01); v0 += u.x + u.y; // (h0,tA)
            u = unpack2(a10); float v1 = u.x + u.y; u = unpack2(a11); v1 += u.x + u.y; // (h1,tA)
            u = unpack2(b00); float v2 = u.x + u.y; u = unpack2(b01); v2 += u.x + u.y; // (h0,tB)
            u = unpack2(b10); float v3 = u.x + u.y; u = unpack2(b11); v3 += u.x + u.y; // (h1,tB)

            // ---- multi-value butterfly reduce: 6 shfl + 4 broadcasts ----
            // stage 1 (off 16): fold (v0,v2) and (v1,v3)
            float p  = hi16 ? v2 : v0;
            float q_ = hi16 ? v0 : v2;
            p += __shfl_xor_sync(FULL, q_, 16);
            float r_ = hi16 ? v3 : v1;
            float s_ = hi16 ? v1 : v3;
            r_ += __shfl_xor_sync(FULL, s_, 16);
            // stage 2 (off 8): fold p (v0|v2) with r_ (v1|v3)
            float t_ = hi8 ? r_ : p;
            float u_ = hi8 ? p : r_;
            t_ += __shfl_xor_sync(FULL, u_, 8);
            // 8-lane butterfly completes each group's value
            t_ += __shfl_xor_sync(FULL, t_, 4);
            t_ += __shfl_xor_sync(FULL, t_, 2);
            t_ += __shfl_xor_sync(FULL, t_, 1);
            // broadcast: groups 0/8/16/24 hold v0/v1/v2/v3
            float sA0 = __shfl_sync(FULL, t_, 0);
            float sA1 = __shfl_sync(FULL, t_, 8);
            float sB0 = __shfl_sync(FULL, t_, 16);
            float sB1 = __shfl_sync(FULL, t_, 24);

            const int gtA = tile * TTILE + tA;
            const int gtB = gtA + 2;
            float lgA0 = (sA0 + sb0) * 0.125f + mask_s[gtA];
            float lgB0 = (sB0 + sb0) * 0.125f + mask_s[gtB];
            float lgA1 = (sA1 + sb1) * 0.125f + mask_s[gtA];
            float lgB1 = (sB1 + sb1) * 0.125f + mask_s[gtB];

            float mx0 = fmaxf(lgA0, lgB0);
            if (mx0 > m0) {
                float scl = __expf(m0 - mx0);  // first: exp(-inf) = 0
                u64 sclp = pack2(scl, scl);
#pragma unroll
                for (int i = 0; i < 8; i++) fmul2(acc0[i], sclp);
                l0 *= scl; m0 = mx0;
            }
            float pA0 = __expf(lgA0 - m0), pB0 = __expf(lgB0 - m0);
            l0 += pA0 + pB0;

            float mx1 = fmaxf(lgA1, lgB1);
            if (mx1 > m1) {
                float scl = __expf(m1 - mx1);
                u64 sclp = pack2(scl, scl);
#pragma unroll
                for (int i = 0; i < 8; i++) fmul2(acc1[i], sclp);
                l1 *= scl; m1 = mx1;
            }
            float pA1 = __expf(lgA1 - m1), pB1 = __expf(lgB1 - m1);
            l1 += pA1 + pB1;

            u64 pvA0 = pack2(pA0, pA0), pvB0 = pack2(pB0, pB0);
            u64 pvA1 = pack2(pA1, pA1), pvB1 = pack2(pB1, pB1);
#pragma unroll
            for (int i = 0; i < 8; i++) {
                ffma2(acc0[i], pvA0, xA[i]);
                ffma2(acc1[i], pvA1, xA[i]);
                ffma2(acc0[i], pvB0, xB[i]);
                ffma2(acc1[i], pvB1, xB[i]);
            }
        }
    }

    // ---- write UNNORMALIZED parity partials + (m, l) ----
    {
        float* p0 = &g_pc[(((long)b * PSPLIT + par) * 8 + h0) * 512 + 4 * lane];
        float* p1 = &g_pc[(((long)b * PSPLIT + par) * 8 + h1) * 512 + 4 * lane];
#pragma unroll
        for (int c = 0; c < 4; c++) {
            float2 v0 = unpack2(acc0[2 * c]), v1 = unpack2(acc0[2 * c + 1]);
            *(float4*)(p0 + 128 * c) = make_float4(v0.x, v0.y, v1.x, v1.y);
            float2 w0 = unpack2(acc1[2 * c]), w1 = unpack2(acc1[2 * c + 1]);
            *(float4*)(p1 + 128 * c) = make_float4(w0.x, w0.y, w1.x, w1.y);
        }
    }
    if (lane == 0) {
        long base = ((long)b * PSPLIT + par) * 16;
        g_pml[base + h0]     = m0;
        g_pml[base + 8 + h0] = l0;
        g_pml[base + h1]     = m1;
        g_pml[base + 8 + h1] = l1;
    }
}

// ============================================================================
// Kernel D: FUSED merge + oproj, SPLIT-K. grid (32, 8, 2) — y = head, z = ks.
// CTA (bB, y, ks) contracts kc in [ks*8, ks*8+8), writes partial to g_po[ks].
// k_ocomb then sums the two partials + bias into out (deterministic).
// ============================================================================
__global__ void __launch_bounds__(256) k_oproj_fused(const float* __restrict__ B)
{
    __shared__ __align__(16) float Cs[3][32][64];   // 24 KB (parity p at +32p)
    __shared__ __align__(16) float Ws[3][64][32];   // 24 KB
    const int tid = threadIdx.x;
    const int bB = blockIdx.x * 32;
    const int y  = blockIdx.y;                       // head
    const int ks = blockIdx.z;                       // K-split half
    const int kc0 = ks * 8;
    const float* Bb = B + (long)y * 64 * 512;
    const int d0 = (tid >> 4) * 4;
    const int b0 = (tid & 15) * 2;

    // per-thread merge weights for its 2 rows (redundant LDG -> L1 broadcast)
    u64 w0p[2], w1p[2];
#pragma unroll
    for (int cb = 0; cb < 2; cb++) {
        int b = bB + b0 + cb;
        float m0 = g_pml[((long)b * PSPLIT + 0) * 16 + y];
        float l0 = g_pml[((long)b * PSPLIT + 0) * 16 + 8 + y];
        float m1 = g_pml[((long)b * PSPLIT + 1) * 16 + y];
        float l1 = g_pml[((long)b * PSPLIT + 1) * 16 + 8 + y];
        float M = fmaxf(m0, m1);
        float e0 = __expf(m0 - M), e1 = __expf(m1 - M);
        float inv = 1.0f / (e0 * l0 + e1 * l1);
        w0p[cb] = pack2(e0 * inv, e0 * inv);
        w1p[cb] = pack2(e1 * inv, e1 * inv);
    }

    u64 acc[2][4];
#pragma unroll
    for (int cb = 0; cb < 2; cb++)
#pragma unroll
        for (int dd = 0; dd < 4; dd++) acc[cb][dd] = 0ull;

    #define OLOAD(buf, kc) do { \
        _Pragma("unroll") for (int i = 0; i < 2; i++) { \
            int idx = tid + 256 * i; \
            int p = idx >> 8, row = (idx >> 3) & 31, cj = idx & 7; \
            long base = (((long)(bB + row) * PSPLIT + p) * 8 + y) * 512; \
            cp16(&Cs[buf][row][32 * p + swz(cj, row)], \
                 (const float*)g_pc + base + (kc) * 32 + cj * 4); \
            int d = idx >> 3, c8 = idx & 7; \
            cp16(&Ws[buf][d][swz(c8, d)], Bb + (long)d * 512 + (kc) * 32 + c8 * 4); \
        } } while (0)

    OLOAD(0, kc0); cp_commit();
    OLOAD(1, kc0 + 1); cp_commit();

    for (int kc = 0; kc < 8; kc++) {
        const int buf = kc % 3;
        cp_wait1();
        __syncthreads();                   // the ONLY barrier per kc

        if (kc + 2 < 8) OLOAD((kc + 2) % 3, kc0 + kc + 2);
        cp_commit();

#pragma unroll
        for (int jg = 0; jg < 8; jg++) {
            ulonglong2 wv[4];
#pragma unroll
            for (int dd = 0; dd < 4; dd++)
                wv[dd] = *(const ulonglong2*)&Ws[buf][d0 + dd][swz(jg, d0 + dd)];
#pragma unroll
            for (int cb = 0; cb < 2; cb++) {
                int rw = b0 + cb;
                ulonglong2 c0 = *(const ulonglong2*)&Cs[buf][rw][swz(jg, rw)];
                ulonglong2 c1 = *(const ulonglong2*)&Cs[buf][rw][32 + swz(jg, rw)];
                u64 t0 = 0ull, t1 = 0ull;
                ffma2(t0, w0p[cb], c0.x); ffma2(t0, w1p[cb], c1.x);
                ffma2(t1, w0p[cb], c0.y); ffma2(t1, w1p[cb], c1.y);
#pragma unroll
                for (int dd = 0; dd < 4; dd++) {
                    ffma2(acc[cb][dd], t0, wv[dd].x);
                    ffma2(acc[cb][dd], t1, wv[dd].y);
                }
            }
        }
    }

#pragma unroll
    for (int cb = 0; cb < 2; cb++) {
        float v[4];
#pragma unroll
        for (int dd = 0; dd < 4; dd++) {
            float2 u = unpack2(acc[cb][dd]);
            v[dd] = u.x + u.y;
        }
        float4 o = make_float4(v[0], v[1], v[2], v[3]);
        *(float4*)&g_po[(long)ks * BS * DM + (long)(bB + b0 + cb) * 512 + y * 64 + d0] = o;
    }
}

// ============================================================================
// Kernel E: combine split-K partials + bias -> out.  grid 512, block 256.
// ============================================================================
__global__ void __launch_bounds__(256) k_ocomb(
    const float* __restrict__ bias, float* __restrict__ out)
{
    int idx4 = blockIdx.x * 256 + threadIdx.x;      // 0..131071 float4s
    long e = (long)idx4 * 4;
    float4 a = *(const float4*)&g_po[e];
    float4 b = *(const float4*)&g_po[(long)BS * DM + e];
    float4 bb = *(const float4*)&bias[(int)(e & 511)];
    float4 o = make_float4(a.x + b.x + bb.x, a.y + b.y + bb.y,
                           a.z + b.z + bb.z, a.w + b.w + bb.w);
    *(float4*)&out[e] = o;
}

// ============================================================================
extern "C" void kernel_launch(void* const* d_in, const int* in_sizes, int n_in,
                              void* d_out, int out_size)
{
    const float* cur  = (const float*)d_in[0];   // [1024, 512]
    const float* prev = (const float*)d_in[1];   // [1024, 199, 512]
    const float* mask = (const float*)d_in[2];   // [1024, 200]
    const float* Wq   = (const float*)d_in[3];   // [512, 512]
    const float* bq   = (const float*)d_in[4];   // [512]
    const float* Wk   = (const float*)d_in[5];   // [512, 512]
    const float* bk   = (const float*)d_in[6];   // [512]
    const float* Wv   = (const float*)d_in[7];   // [512, 512]
    const float* bv   = (const float*)d_in[8];   // [512]
    float* out = (float*)d_out;                  // [1024, 512]

    // q = cur @ Wq^T + bq          (writes g_q internally)
    k_qproj<<<dim3(32, 8), 256>>>(cur, Wq, bq);
    // r[b,h,:] = Wk_h^T q_h        (g_q -> g_r)
    k_rproj<<<dim3(4, 32, 8), 256>>>(Wk);
    // lane-distinct attention      (-> g_pc, g_pml)
    k_attn <<<dim3(1024), 256>>>(cur, prev, mask, bk);
    // fused merge + out-projection, split-K (-> g_po)
    k_oproj_fused<<<dim3(32, 8, 2), 256>>>(Wv);
    // combine partials + bias      (-> out)
    k_ocomb<<<512, 256>>>(bv, out);
}